// round 16
// baseline (speedup 1.0000x reference)
#include <cuda_runtime.h>

typedef unsigned long long u64;
typedef unsigned int u32;

#define BATCH 16
#define IMG_H 512
#define IMG_W 512
#define NPIX (IMG_H * IMG_W)      // 262144
#define TOTAL (BATCH * NPIX)      // 4194304
#define WPR 8                     // 64-bit words per row
#define ROWS (BATCH * IMG_H)      // 8192
#define NW (TOTAL / 64)           // 65536
#define WPI (NPIX / 64)           // 4096
#define MAXR 32768                // max runs per image (R12 passed with 16384)

// Scratch (allocation-free)
__device__ u64 g_m0[NW];
__device__ u64 g_m1[NW];
__device__ u64 g_m2[NW];
__device__ int g_prevcnt[NW];          // global run-id base per word
__device__ int g_parent[BATCH * MAXR];
__device__ int g_csize[BATCH * MAXR];
__device__ int g_nruns[BATCH];
__device__ int g_ncomp[BATCH];

__device__ __forceinline__ u64* mbuf(int s) {
    return s == 0 ? g_m0 : (s == 1 ? g_m1 : g_m2);
}

// ---------------------------------------------------------------------------
// SE half-widths (compile-time)
// ---------------------------------------------------------------------------
template <int R>
__device__ __forceinline__ constexpr int hw_disk(int dy) {
    int best = 0;
    for (int x = 0; x <= R; x++)
        if (x * x + dy * dy <= R * R) best = x;
    return best;
}
// disk(2) (+) disk(5) Minkowski sum
__device__ __forceinline__ constexpr int hw_comb(int dy) {
    int best = 0;
    for (int a = -5; a <= 5; a++) {
        int b = dy - a;
        if (b < -2 || b > 2) continue;
        int h5 = 0, h2 = 0;
        for (int x = 0; x <= 5; x++) if (x * x + a * a <= 25) h5 = x;
        for (int x = 0; x <= 2; x++) if (x * x + b * b <= 4)  h2 = x;
        if (h5 + h2 > best) best = h5 + h2;
    }
    return best;
}

// segment helpers
__device__ __forceinline__ int seg_len(u64 rem, int j) {
    u64 inv = ~(rem >> j);
    return inv ? (__ffsll((long long)inv) - 1) : (64 - j);
}
__device__ __forceinline__ u64 seg_bits(int j, int len) {
    return (j + len >= 64) ? (~0ull << j) : (((1ull << len) - 1ull) << j);
}
__device__ __forceinline__ u64 below_incl(int j) {
    return (j == 63) ? ~0ull : ((2ull << j) - 1ull);
}

// ---------------------------------------------------------------------------
// Pack / unpack
// ---------------------------------------------------------------------------
__global__ void k_binarize(const float* __restrict__ in, int dst) {
    int g = blockIdx.x * blockDim.x + threadIdx.x;
    if (g >= TOTAL) return;
    unsigned b = __ballot_sync(0xffffffffu, in[g] > 0.0f);
    if ((threadIdx.x & 31) == 0) ((u32*)mbuf(dst))[g >> 5] = b;
}

// ---------------------------------------------------------------------------
// Morphology — no early exit (loads stay branch-independent => high MLP)
// ---------------------------------------------------------------------------
template <int R, bool COMB>
__global__ void k_erode(int src, int dst) {
    int wg = blockIdx.x * blockDim.x + threadIdx.x;
    if (wg >= NW) return;
    const u64* __restrict__ in = mbuf(src);
    int w = wg & (WPR - 1);
    int y = (wg / WPR) & (IMG_H - 1);
    u64 acc = ~0ull;
#pragma unroll
    for (int dy = -R; dy <= R; dy++) {
        int yy = y + dy;
        if (yy < 0 || yy >= IMG_H) continue;     // OOB row counts as 1
        int rw = wg + dy * WPR;
        u64 mid = in[rw];
        u64 lo = (w == 0) ? ~0ull : in[rw - 1];
        u64 hi = (w == WPR - 1) ? ~0ull : in[rw + 1];
        u64 a = mid;
        const int h = COMB ? hw_comb(dy) : hw_disk<R>(dy);
#pragma unroll
        for (int k = 1; k <= h; k++) {
            a &= (mid >> k) | (hi << (64 - k));
            a &= (mid << k) | (lo >> (64 - k));
        }
        acc &= a;
    }
    mbuf(dst)[wg] = acc;
}

template <int R>
__global__ void k_dilate(int src, int dst) {
    int wg = blockIdx.x * blockDim.x + threadIdx.x;
    if (wg >= NW) return;
    const u64* __restrict__ in = mbuf(src);
    int w = wg & (WPR - 1);
    int y = (wg / WPR) & (IMG_H - 1);
    u64 acc = 0ull;
#pragma unroll
    for (int dy = -R; dy <= R; dy++) {
        int yy = y + dy;
        if (yy < 0 || yy >= IMG_H) continue;     // OOB row counts as 0
        int rw = wg + dy * WPR;
        u64 mid = in[rw];
        u64 lo = (w == 0) ? 0ull : in[rw - 1];
        u64 hi = (w == WPR - 1) ? 0ull : in[rw + 1];
        u64 a = mid;
        const int h = hw_disk<R>(dy);
#pragma unroll
        for (int k = 1; k <= h; k++) {
            a |= (mid >> k) | (hi << (64 - k));
            a |= (mid << k) | (lo >> (64 - k));
        }
        acc |= a;
    }
    mbuf(dst)[wg] = acc;
}

// dilate disk(1) fused with float unpack (warp per word, coalesced stores)
__global__ void k_dilate1_out(int src, float* __restrict__ out) {
    int warp = (blockIdx.x * blockDim.x + threadIdx.x) >> 5;
    int lane = threadIdx.x & 31;
    if (warp >= NW) return;
    const u64* __restrict__ in = mbuf(src);
    int wg = warp;
    int w = wg & (WPR - 1);
    int y = (wg / WPR) & (IMG_H - 1);
    u64 mid = in[wg];
    u64 lo = (w == 0) ? 0ull : in[wg - 1];
    u64 hi = (w == WPR - 1) ? 0ull : in[wg + 1];
    u64 a = mid | ((mid >> 1) | (hi << 63)) | ((mid << 1) | (lo >> 63));
    if (y > 0)          a |= in[wg - WPR];
    if (y < IMG_H - 1)  a |= in[wg + WPR];
    long long base = (long long)wg * 64;
    out[base + lane]      = ((a >> lane) & 1ull) ? 1.0f : 0.0f;
    out[base + 32 + lane] = ((a >> (lane + 32)) & 1ull) ? 1.0f : 0.0f;
}

// ---------------------------------------------------------------------------
// CCL with compact run IDs
// ---------------------------------------------------------------------------
__device__ __forceinline__ int uf_find(int i) {
    int p = g_parent[i];
    while (p != i) { i = p; p = g_parent[i]; }
    return i;
}
__device__ void uf_merge(int a, int b) {
    while (true) {
        a = uf_find(a);
        b = uf_find(b);
        if (a == b) return;
        int lo = a < b ? a : b;
        int hi = a < b ? b : a;
        int old = atomicMin(&g_parent[hi], lo);
        if (old == hi) return;
        a = lo; b = old;
    }
}

// One block per image, 512 threads (one row each): count runs, scan, assign IDs.
__global__ void k_prep(int src) {
    __shared__ int sa[IMG_H], sb[IMG_H];
    int img = blockIdx.x;
    int r = threadIdx.x;                 // 0..511
    const u64* __restrict__ M = mbuf(src) + img * WPI;

    // count runs in this row
    int cnt = 0; u64 prevtop = 0;
#pragma unroll
    for (int w = 0; w < WPR; w++) {
        u64 m = M[r * WPR + w];
        cnt += __popcll(m & ~((m << 1) | prevtop));
        prevtop = m >> 63;
    }
    sa[r] = cnt;
    __syncthreads();

    // inclusive scan over 512 rows (Hillis-Steele, ping-pong)
    int* cur = sa; int* nxt = sb;
#pragma unroll
    for (int d = 1; d < IMG_H; d <<= 1) {
        nxt[r] = cur[r] + ((r >= d) ? cur[r - d] : 0);
        __syncthreads();
        int* t = cur; cur = nxt; nxt = t;
    }
    int rowbase = (r ? cur[r - 1] : 0);
    if (r == 0) { g_nruns[img] = cur[IMG_H - 1]; g_ncomp[img] = 0; }

    // assign: prevcnt per word, parent/csize per run
    int base = img * MAXR + rowbase;
    int c = 0, curlen = 0;
    bool open = false;
    prevtop = 0;
#pragma unroll
    for (int w = 0; w < WPR; w++) {
        int gw = img * WPI + r * WPR + w;
        g_prevcnt[gw] = base + c;
        u64 m = M[r * WPR + w];
        u64 rem = m;
        while (rem) {
            int j = __ffsll((long long)rem) - 1;
            int len = seg_len(rem, j);
            if (j == 0 && open && prevtop) {
                curlen += len;                       // continuation across words
            } else {
                if (open) { int id = base + c - 1; g_parent[id] = id; g_csize[id] = curlen; }
                open = true; c++; curlen = len;
            }
            rem &= ~seg_bits(j, len);
        }
        prevtop = m >> 63;
    }
    if (open) { int id = base + c - 1; g_parent[id] = id; g_csize[id] = curlen; }
}

// per word: merge vertically-adjacent runs
__global__ void k_merge(int src) {
    int g = blockIdx.x * blockDim.x + threadIdx.x;
    if (g >= NW) return;
    int r = g >> 3;
    if ((r & (IMG_H - 1)) == 0) return;            // first row of image
    const u64* __restrict__ M = mbuf(src);
    u64 cm = M[g], um = M[g - WPR];
    u64 both = cm & um;
    if (!both) return;
    int wx = g & (WPR - 1);
    u64 ptc = wx ? (M[g - 1] >> 63) : 0;
    u64 ptu = wx ? (M[g - WPR - 1] >> 63) : 0;
    u64 stc = cm & ~((cm << 1) | ptc);
    u64 stu = um & ~((um << 1) | ptu);
    int bc = g_prevcnt[g], bu = g_prevcnt[g - WPR];
    u64 rem = both;
    while (rem) {
        int j = __ffsll((long long)rem) - 1;
        int len = seg_len(rem, j);
        u64 bel = below_incl(j);
        uf_merge(bc + __popcll(stc & bel) - 1, bu + __popcll(stu & bel) - 1);
        rem &= ~seg_bits(j, len);
    }
}

// per run id: compress to root, accumulate sizes, count roots
__global__ void k_finalize() {
    int id = blockIdx.x * blockDim.x + threadIdx.x;
    if (id >= BATCH * MAXR) return;
    int img = id / MAXR;
    int local = id - img * MAXR;
    if (local >= g_nruns[img]) return;
    int root = uf_find(id);
    if (root != id) {
        g_parent[id] = root;
        atomicAdd(&g_csize[root], g_csize[id]);
    } else {
        atomicAdd(&g_ncomp[img], 1);
    }
}

// per word: filter. MODE 0: keep-big (guard). 1: keep-big, inverted output.
// 2: hole fill (src = bg; out = ~bg | small-bg-segments).
template <int MODE>
__global__ void k_filter(int src, int dst, int min_size) {
    int g = blockIdx.x * blockDim.x + threadIdx.x;
    if (g >= NW) return;
    const u64* __restrict__ M = mbuf(src);
    u64 m = M[g];
    u64 out = (MODE == 2) ? ~m : 0ull;
    if (m) {
        int wx = g & (WPR - 1);
        u64 pt = wx ? (M[g - 1] >> 63) : 0;
        u64 st = m & ~((m << 1) | pt);
        int base = g_prevcnt[g];
        bool keepall = (MODE != 2) && (g_ncomp[g / WPI] <= 1);
        u64 rem = m;
        while (rem) {
            int j = __ffsll((long long)rem) - 1;
            int len = seg_len(rem, j);
            int id = base + __popcll(st & below_incl(j)) - 1;
            int sz = g_csize[g_parent[id]];
            u64 bits = seg_bits(j, len);
            if (MODE == 2) { if (sz < min_size) out |= bits; }
            else           { if (keepall || sz >= min_size) out |= bits; }
            rem &= ~bits;
        }
    }
    mbuf(dst)[g] = (MODE == 1) ? ~out : out;
}

// ---------------------------------------------------------------------------
// Launch
// ---------------------------------------------------------------------------
extern "C" void kernel_launch(void* const* d_in, const int* in_sizes, int n_in,
                              void* d_out, int out_size) {
    const float* in = (const float*)d_in[0];
    float* out = (float*)d_out;

    const int T = 256;
    const int Bpix = TOTAL / T;                    // 16384
    const int Bw = NW / T;                         // 256
    const int Bfin = (BATCH * MAXR) / T;           // 2048

    // fg0 -> m0
    k_binarize<<<Bpix, T>>>(in, 0);

    // remove_small_objects(m0, 2000, guard); output bg = ~kept -> m1
    k_prep<<<BATCH, IMG_H>>>(0);
    k_merge<<<Bw, T>>>(0);
    k_finalize<<<Bfin, T>>>();
    k_filter<1><<<Bw, T>>>(0, 1, 2000);

    // hole fill: CCL on bg (m1) -> m0
    k_prep<<<BATCH, IMG_H>>>(1);
    k_merge<<<Bw, T>>>(1);
    k_finalize<<<Bfin, T>>>();
    k_filter<2><<<Bw, T>>>(1, 0, 301);

    // erode disk2 then disk5 fused (Minkowski): m0 -> m1 ; dilate disk5: m1 -> m2
    k_erode<7, true><<<Bw, T>>>(0, 1);
    k_dilate<5><<<Bw, T>>>(1, 2);

    // remove_small_objects(m2, 2000, guard) -> m0
    k_prep<<<BATCH, IMG_H>>>(2);
    k_merge<<<Bw, T>>>(2);
    k_finalize<<<Bfin, T>>>();
    k_filter<0><<<Bw, T>>>(2, 0, 2000);

    // dilate disk1 + unpack to float
    k_dilate1_out<<<NW / (T / 32), T>>>(0, out);
}